// round 1
// baseline (speedup 1.0000x reference)
#include <cuda_runtime.h>

// Dims (fixed by the problem)
#define RVD 4
#define RD 16
#define F_IN 64
#define F_OUT 64
#define BVD 16              // B*V
#define ROWS_PER_BV 65536   // T*N*D = 4*1024*16
#define TILE 256
#define NTILES (ROWS_PER_BV / TILE)  // 256
#define BLOCK 256
#define GRIDX 64

// Precomputed per-(b,v) combined factor: G1[bv][a][c] = sum_B fac_in[B,a] * (sum_A fv[bv,A]*core[A,B,c])
__device__ float g_G1[BVD * F_IN * RD];

// smem floats: xs[TILE*64] + ys[TILE*17] + G1s[64*16]
#define SMEM_FLOATS (TILE * 64 + TILE * 17 + F_IN * RD)
#define SMEM_BYTES (SMEM_FLOATS * 4)

__global__ void prep_kernel(const int* __restrict__ var_idx,
                            const float* __restrict__ core,
                            const float* __restrict__ factor_vars,
                            const float* __restrict__ fac_in) {
    int bv = blockIdx.x;     // 0..15
    int t = threadIdx.x;     // 0..63  (= 'a' index in second phase)
    __shared__ float W[RD][RD];
    int vi = var_idx[bv];

    // W[b][c] = sum_A fv[A] * core[A][b][c]; 256 entries, 4 per thread
    #pragma unroll
    for (int k = 0; k < 4; k++) {
        int idx = t * 4 + k;
        int b = idx >> 4, c = idx & 15;
        float s = 0.f;
        #pragma unroll
        for (int A = 0; A < RVD; A++)
            s += factor_vars[vi * RVD + A] * core[(A * RD + b) * RD + c];
        W[b][c] = s;
    }
    __syncthreads();

    // G1[a][c] = sum_b fac_in[b][a] * W[b][c]
    float fin[RD];
    #pragma unroll
    for (int b = 0; b < RD; b++) fin[b] = fac_in[b * F_IN + t];
    #pragma unroll
    for (int c = 0; c < RD; c++) {
        float s = 0.f;
        #pragma unroll
        for (int b = 0; b < RD; b++) s += fin[b] * W[b][c];
        g_G1[(bv * F_IN + t) * RD + c] = s;
    }
}

extern __shared__ float smem[];

__global__ __launch_bounds__(BLOCK, 2)
void tucker_main(const float* __restrict__ x,
                 const float* __restrict__ fac_out,
                 float* __restrict__ out) {
    float* xs  = smem;                   // TILE*64, XOR-swizzled float4 chunks
    float* ys  = xs + TILE * 64;         // TILE*17 (padded rows)
    float* G1s = ys + TILE * 17;         // 64*16

    const int tid = threadIdx.x;
    const int bv  = blockIdx.y;

    // Load this bv's G1 into smem
    for (int i = tid; i < F_IN * RD; i += BLOCK)
        G1s[i] = g_G1[bv * F_IN * RD + i];

    // Each thread owns output columns e = 4*eg .. 4*eg+3; fac_out column slice in regs
    const int eg = tid & 15;
    float4 fo[16];
    #pragma unroll
    for (int j = 0; j < 16; j++)
        fo[j] = *reinterpret_cast<const float4*>(fac_out + j * F_OUT + eg * 4);

    __syncthreads();

    const size_t bvbase = (size_t)bv * ROWS_PER_BV * 64;

    const int j4 = tid & 3;    // rank-col group (4 cols)
    const int rg = tid >> 2;   // row group: rows rg*4 .. rg*4+3
    const int swz = rg & 15;   // xs swizzle key for these 4 rows ( (r>>2)&15 )

    for (int tile = blockIdx.x; tile < NTILES; tile += gridDim.x) {
        const float4* xt = reinterpret_cast<const float4*>(x + bvbase + (size_t)tile * TILE * 64);

        // ---- stage x tile: 256 rows x 16 float4, coalesced, XOR swizzle on chunk index ----
        #pragma unroll
        for (int i = 0; i < 16; i++) {
            int fi = i * BLOCK + tid;        // linear float4 index in tile
            float4 v = xt[fi];
            int r = fi >> 4, c4 = fi & 15;
            int pos = r * 16 + (c4 ^ ((r >> 2) & 15));
            reinterpret_cast<float4*>(xs)[pos] = v;
        }
        __syncthreads();

        // ---- Y stage: ys[r][c] = sum_a xs[r][a] * G1s[a][c]; thread = 4 rows x 4 c ----
        {
            float a00 = 0.f, a01 = 0.f, a02 = 0.f, a03 = 0.f;
            float a10 = 0.f, a11 = 0.f, a12 = 0.f, a13 = 0.f;
            float a20 = 0.f, a21 = 0.f, a22 = 0.f, a23 = 0.f;
            float a30 = 0.f, a31 = 0.f, a32 = 0.f, a33 = 0.f;
            const int r0 = rg * 4;
            const float* xbase = xs + r0 * 64;

            #pragma unroll 16
            for (int a = 0; a < 64; a++) {
                int col = (((a >> 2) ^ swz) << 2) + (a & 3);   // de-swizzled column
                float xa0 = xbase[col];
                float xa1 = xbase[col + 64];
                float xa2 = xbase[col + 128];
                float xa3 = xbase[col + 192];
                float4 g = *reinterpret_cast<const float4*>(&G1s[a * RD + j4 * 4]);
                a00 += xa0 * g.x; a01 += xa0 * g.y; a02 += xa0 * g.z; a03 += xa0 * g.w;
                a10 += xa1 * g.x; a11 += xa1 * g.y; a12 += xa1 * g.z; a13 += xa1 * g.w;
                a20 += xa2 * g.x; a21 += xa2 * g.y; a22 += xa2 * g.z; a23 += xa2 * g.w;
                a30 += xa3 * g.x; a31 += xa3 * g.y; a32 += xa3 * g.z; a33 += xa3 * g.w;
            }
            float* y0 = ys + (r0 + 0) * 17 + j4 * 4;
            float* y1 = ys + (r0 + 1) * 17 + j4 * 4;
            float* y2 = ys + (r0 + 2) * 17 + j4 * 4;
            float* y3 = ys + (r0 + 3) * 17 + j4 * 4;
            y0[0] = a00; y0[1] = a01; y0[2] = a02; y0[3] = a03;
            y1[0] = a10; y1[1] = a11; y1[2] = a12; y1[3] = a13;
            y2[0] = a20; y2[1] = a21; y2[2] = a22; y2[3] = a23;
            y3[0] = a30; y3[1] = a31; y3[2] = a32; y3[3] = a33;
        }
        __syncthreads();

        // ---- out stage: out[r][e] = sum_c ys[r][c]*fac_out[c][e]; thread = fixed 4-wide e-group ----
        float4* ot = reinterpret_cast<float4*>(out + bvbase + (size_t)tile * TILE * 64);
        #pragma unroll
        for (int it = 0; it < 16; it++) {
            int r = (tid >> 4) + it * 16;
            const float* yr = ys + r * 17;
            float ax = 0.f, ay = 0.f, az = 0.f, aw = 0.f;
            #pragma unroll
            for (int j = 0; j < 16; j++) {
                float yv = yr[j];
                ax += yv * fo[j].x;
                ay += yv * fo[j].y;
                az += yv * fo[j].z;
                aw += yv * fo[j].w;
            }
            float4 o; o.x = ax; o.y = ay; o.z = az; o.w = aw;
            ot[r * 16 + eg] = o;   // lanes 0..15 cover one full 256B row -> coalesced
        }
        __syncthreads();
    }
}

extern "C" void kernel_launch(void* const* d_in, const int* in_sizes, int n_in,
                              void* d_out, int out_size) {
    const float* x           = (const float*)d_in[0];
    const int*   var_idx     = (const int*)d_in[1];
    const float* core        = (const float*)d_in[2];
    const float* factor_vars = (const float*)d_in[3];
    const float* fac_in      = (const float*)d_in[4];
    const float* fac_out     = (const float*)d_in[5];
    float* out = (float*)d_out;

    cudaFuncSetAttribute(tucker_main, cudaFuncAttributeMaxDynamicSharedMemorySize, SMEM_BYTES);

    prep_kernel<<<BVD, 64>>>(var_idx, core, factor_vars, fac_in);

    dim3 grid(GRIDX, BVD);
    tucker_main<<<grid, BLOCK, SMEM_BYTES>>>(x, fac_out, out);
}

// round 2
// speedup vs baseline: 1.2260x; 1.2260x over previous
#include <cuda_runtime.h>

// Fixed dims
#define RVD 4
#define RD 16
#define F_IN 64
#define F_OUT 64
#define BVD 16              // B*V
#define ROWS_PER_BV 65536   // T*N*D
#define TILE 256
#define NTILES (ROWS_PER_BV / TILE)   // 256
#define BLOCK 256

// Per-bv combined factor, TRANSPOSED [c][a] and pre-swizzled in float4 chunks:
// element (c, a) lives at  c*64 + (( (a>>2) ^ (c>>2) )<<2) + (a&3)
__device__ float g_G1t[BVD * RD * F_IN];

// smem: xs (TILE*64 floats, swizzled f4 chunks) + ys (TILE*20, padded rows) + g1 (1024)
#define YS_STRIDE 20
#define SMEM_FLOATS (TILE * 64 + TILE * YS_STRIDE + RD * F_IN)
#define SMEM_BYTES  (SMEM_FLOATS * 4)

__device__ __forceinline__ void cp16(float* dst_smem, const float* src_gmem) {
    unsigned d = (unsigned)__cvta_generic_to_shared(dst_smem);
    asm volatile("cp.async.cg.shared.global [%0], [%1], 16;\n" :: "r"(d), "l"(src_gmem));
}
__device__ __forceinline__ void cp_commit_wait() {
    asm volatile("cp.async.commit_group;\n");
    asm volatile("cp.async.wait_group 0;\n");
}

// ---------------- prep: G1t[bv][c][a] = sum_B fac_in[B,a] * (sum_A fv[bv,A]*core[A,B,c]) ----
__global__ void prep_kernel(const int* __restrict__ var_idx,
                            const float* __restrict__ core,
                            const float* __restrict__ factor_vars,
                            const float* __restrict__ fac_in) {
    int bv = blockIdx.x;     // 0..15
    int t = threadIdx.x;     // 0..63  (= 'a')
    __shared__ float W[RD][RD];
    int vi = var_idx[bv];

    #pragma unroll
    for (int kk = 0; kk < 4; kk++) {
        int idx = t * 4 + kk;
        int b = idx >> 4, c = idx & 15;
        float s = 0.f;
        #pragma unroll
        for (int A = 0; A < RVD; A++)
            s += factor_vars[vi * RVD + A] * core[(A * RD + b) * RD + c];
        W[b][c] = s;
    }
    __syncthreads();

    float fin[RD];
    #pragma unroll
    for (int b = 0; b < RD; b++) fin[b] = fac_in[b * F_IN + t];

    int k = t >> 2, m = t & 3;   // a-chunk, lane within chunk
    #pragma unroll
    for (int c = 0; c < RD; c++) {
        float s = 0.f;
        #pragma unroll
        for (int b = 0; b < RD; b++) s += fin[b] * W[b][c];
        int col = k ^ (c >> 2);                       // swizzled chunk column
        g_G1t[bv * (RD * F_IN) + c * 64 + (col << 2) + m] = s;
    }
}

// ---------------- main ----------------
extern __shared__ float smem[];

__global__ __launch_bounds__(BLOCK, 2)
void tucker_main(const float* __restrict__ x,
                 const float* __restrict__ fac_out,
                 float* __restrict__ out) {
    float* xs = smem;                        // TILE*64
    float* ys = xs + TILE * 64;              // TILE*YS_STRIDE
    float* g1 = ys + TILE * YS_STRIDE;       // 1024

    const int tid  = threadIdx.x;
    const int bv   = blockIdx.y;
    const int tile = blockIdx.x;

    const size_t base = (size_t)bv * ROWS_PER_BV * 64 + (size_t)tile * TILE * 64;
    const float* xsrc = x + base;

    // ---- stage x tile + G1t via cp.async (swizzled dst) ----
    #pragma unroll
    for (int i = 0; i < 16; i++) {
        int fi = i * BLOCK + tid;            // float4 linear index in tile
        int r = fi >> 4, c4 = fi & 15;
        int pos = r * 16 + (c4 ^ ((r >> 2) & 7));
        cp16(xs + (pos << 2), xsrc + (fi << 2));
    }
    cp16(g1 + (tid << 2), g_G1t + bv * (RD * F_IN) + (tid << 2));
    cp_commit_wait();
    __syncthreads();

    // ---- Y stage: thread = 4 rows x 4 contiguous c ----
    {
        const int rg = tid >> 2;             // 0..63 -> rows rg*4..rg*4+3
        const int j4 = tid & 3;              // c block: c = j4*4..j4*4+3
        const int r0 = rg * 4;
        const int xkey = rg & 7;
        const float4* xs4 = reinterpret_cast<const float4*>(xs);
        const float4* g14 = reinterpret_cast<const float4*>(g1);

        float a00=0.f,a01=0.f,a02=0.f,a03=0.f;
        float a10=0.f,a11=0.f,a12=0.f,a13=0.f;
        float a20=0.f,a21=0.f,a22=0.f,a23=0.f;
        float a30=0.f,a31=0.f,a32=0.f,a33=0.f;

        #pragma unroll 4
        for (int k = 0; k < 16; k++) {
            float4 x0 = xs4[(r0 + 0) * 16 + (k ^ xkey)];
            float4 x1 = xs4[(r0 + 1) * 16 + (k ^ xkey)];
            float4 x2 = xs4[(r0 + 2) * 16 + (k ^ xkey)];
            float4 x3 = xs4[(r0 + 3) * 16 + (k ^ xkey)];
            int gc = k ^ j4;
            float4 g0 = g14[(j4 * 4 + 0) * 16 + gc];
            float4 g1v = g14[(j4 * 4 + 1) * 16 + gc];
            float4 g2 = g14[(j4 * 4 + 2) * 16 + gc];
            float4 g3 = g14[(j4 * 4 + 3) * 16 + gc];

            a00 += x0.x*g0.x + x0.y*g0.y + x0.z*g0.z + x0.w*g0.w;
            a01 += x0.x*g1v.x + x0.y*g1v.y + x0.z*g1v.z + x0.w*g1v.w;
            a02 += x0.x*g2.x + x0.y*g2.y + x0.z*g2.z + x0.w*g2.w;
            a03 += x0.x*g3.x + x0.y*g3.y + x0.z*g3.z + x0.w*g3.w;
            a10 += x1.x*g0.x + x1.y*g0.y + x1.z*g0.z + x1.w*g0.w;
            a11 += x1.x*g1v.x + x1.y*g1v.y + x1.z*g1v.z + x1.w*g1v.w;
            a12 += x1.x*g2.x + x1.y*g2.y + x1.z*g2.z + x1.w*g2.w;
            a13 += x1.x*g3.x + x1.y*g3.y + x1.z*g3.z + x1.w*g3.w;
            a20 += x2.x*g0.x + x2.y*g0.y + x2.z*g0.z + x2.w*g0.w;
            a21 += x2.x*g1v.x + x2.y*g1v.y + x2.z*g1v.z + x2.w*g1v.w;
            a22 += x2.x*g2.x + x2.y*g2.y + x2.z*g2.z + x2.w*g2.w;
            a23 += x2.x*g3.x + x2.y*g3.y + x2.z*g3.z + x2.w*g3.w;
            a30 += x3.x*g0.x + x3.y*g0.y + x3.z*g0.z + x3.w*g0.w;
            a31 += x3.x*g1v.x + x3.y*g1v.y + x3.z*g1v.z + x3.w*g1v.w;
            a32 += x3.x*g2.x + x3.y*g2.y + x3.z*g2.z + x3.w*g2.w;
            a33 += x3.x*g3.x + x3.y*g3.y + x3.z*g3.z + x3.w*g3.w;
        }
        *reinterpret_cast<float4*>(ys + (r0 + 0) * YS_STRIDE + j4 * 4) = make_float4(a00,a01,a02,a03);
        *reinterpret_cast<float4*>(ys + (r0 + 1) * YS_STRIDE + j4 * 4) = make_float4(a10,a11,a12,a13);
        *reinterpret_cast<float4*>(ys + (r0 + 2) * YS_STRIDE + j4 * 4) = make_float4(a20,a21,a22,a23);
        *reinterpret_cast<float4*>(ys + (r0 + 3) * YS_STRIDE + j4 * 4) = make_float4(a30,a31,a32,a33);
    }
    __syncthreads();

    // ---- out stage: thread owns e-group eg (4 output cols) across 16 rows ----
    {
        const int eg = tid & 15;
        const int rbase = tid >> 4;

        float4 fo[16];
        #pragma unroll
        for (int j = 0; j < 16; j++)
            fo[j] = *reinterpret_cast<const float4*>(fac_out + j * F_OUT + eg * 4);

        float4* ot = reinterpret_cast<float4*>(out + base);

        #pragma unroll 4
        for (int it = 0; it < 16; it++) {
            int r = rbase + it * 16;
            const float4* yr = reinterpret_cast<const float4*>(ys + r * YS_STRIDE);
            float4 y0 = yr[0], y1 = yr[1], y2 = yr[2], y3 = yr[3];

            float ax, ay, az, aw;
            ax = y0.x*fo[0].x;  ay = y0.x*fo[0].y;  az = y0.x*fo[0].z;  aw = y0.x*fo[0].w;
            ax += y0.y*fo[1].x; ay += y0.y*fo[1].y; az += y0.y*fo[1].z; aw += y0.y*fo[1].w;
            ax += y0.z*fo[2].x; ay += y0.z*fo[2].y; az += y0.z*fo[2].z; aw += y0.z*fo[2].w;
            ax += y0.w*fo[3].x; ay += y0.w*fo[3].y; az += y0.w*fo[3].z; aw += y0.w*fo[3].w;
            ax += y1.x*fo[4].x; ay += y1.x*fo[4].y; az += y1.x*fo[4].z; aw += y1.x*fo[4].w;
            ax += y1.y*fo[5].x; ay += y1.y*fo[5].y; az += y1.y*fo[5].z; aw += y1.y*fo[5].w;
            ax += y1.z*fo[6].x; ay += y1.z*fo[6].y; az += y1.z*fo[6].z; aw += y1.z*fo[6].w;
            ax += y1.w*fo[7].x; ay += y1.w*fo[7].y; az += y1.w*fo[7].z; aw += y1.w*fo[7].w;
            ax += y2.x*fo[8].x; ay += y2.x*fo[8].y; az += y2.x*fo[8].z; aw += y2.x*fo[8].w;
            ax += y2.y*fo[9].x; ay += y2.y*fo[9].y; az += y2.y*fo[9].z; aw += y2.y*fo[9].w;
            ax += y2.z*fo[10].x;ay += y2.z*fo[10].y;az += y2.z*fo[10].z;aw += y2.z*fo[10].w;
            ax += y2.w*fo[11].x;ay += y2.w*fo[11].y;az += y2.w*fo[11].z;aw += y2.w*fo[11].w;
            ax += y3.x*fo[12].x;ay += y3.x*fo[12].y;az += y3.x*fo[12].z;aw += y3.x*fo[12].w;
            ax += y3.y*fo[13].x;ay += y3.y*fo[13].y;az += y3.y*fo[13].z;aw += y3.y*fo[13].w;
            ax += y3.z*fo[14].x;ay += y3.z*fo[14].y;az += y3.z*fo[14].z;aw += y3.z*fo[14].w;
            ax += y3.w*fo[15].x;ay += y3.w*fo[15].y;az += y3.w*fo[15].z;aw += y3.w*fo[15].w;

            ot[r * 16 + eg] = make_float4(ax, ay, az, aw);
        }
    }
}

extern "C" void kernel_launch(void* const* d_in, const int* in_sizes, int n_in,
                              void* d_out, int out_size) {
    const float* x           = (const float*)d_in[0];
    const int*   var_idx     = (const int*)d_in[1];
    const float* core        = (const float*)d_in[2];
    const float* factor_vars = (const float*)d_in[3];
    const float* fac_in      = (const float*)d_in[4];
    const float* fac_out     = (const float*)d_in[5];
    float* out = (float*)d_out;

    cudaFuncSetAttribute(tucker_main, cudaFuncAttributeMaxDynamicSharedMemorySize, SMEM_BYTES);

    prep_kernel<<<BVD, 64>>>(var_idx, core, factor_vars, fac_in);

    dim3 grid(NTILES, BVD);
    tucker_main<<<grid, BLOCK, SMEM_BYTES>>>(x, fac_out, out);
}